// round 4
// baseline (speedup 1.0000x reference)
#include <cuda_runtime.h>
#include <cstdint>

#define N_NODES 50000
#define C_DIM   128
#define E_EDGES 800000
#define NBUCK   65536
#define CANDMAX 2048

// ---------------- scratch (static device globals; no allocation) ----------------
__device__ float    g_deg[N_NODES];
__device__ float    g_dinv[N_NODES];
__device__ __align__(16) float g_agg[N_NODES * C_DIM];   // 25.6 MB
__device__ unsigned g_keys[N_NODES];
__device__ int      g_hist[NBUCK];
__device__ int      g_cnt;
__device__ int      g_thresh;
__device__ unsigned g_candk[CANDMAX];
__device__ int      g_candi[CANDMAX];
__device__ float    g_pinv;
__device__ __align__(16) float g_Xt[C_DIM * C_DIM];
__device__ __align__(16) float g_gi[C_DIM * 3 * C_DIM];
__device__ __align__(16) float g_gh[C_DIM * 3 * C_DIM];
__device__ __align__(16) float g_Wnew[C_DIM * C_DIM];

// ---------------- 1/||p|| ----------------
__global__ void k_pnorm(const float* __restrict__ p) {
    __shared__ float sh[128];
    float v = p[threadIdx.x];
    sh[threadIdx.x] = v * v;
    __syncthreads();
    for (int s = 64; s > 0; s >>= 1) {
        if (threadIdx.x < s) sh[threadIdx.x] += sh[threadIdx.x + s];
        __syncthreads();
    }
    if (threadIdx.x == 0) g_pinv = rsqrtf(sh[0]);
}

// ---------------- init: hist=0, deg=1 (self-loop weight), counters ----------------
__global__ void k_init() {
    int i = blockIdx.x * blockDim.x + threadIdx.x;
    if (i < NBUCK)   g_hist[i] = 0;
    if (i < N_NODES) g_deg[i] = 1.0f;
    if (i == 0)      g_cnt = 0;
}

// ---------------- degree accumulation (edge_index is INT32) ----------------
__global__ void k_deg(const int* __restrict__ ei, const float* __restrict__ ew) {
    int e = blockIdx.x * 256 + threadIdx.x;
    if (e < E_EDGES) {
        int dst = ei[E_EDGES + e];
        atomicAdd(&g_deg[dst], ew[e]);
    }
}

// ---------------- dinv + agg init with self-loop term (warp per node) ----------------
__global__ void k_dinv_agg(const float* __restrict__ X) {
    int w    = (blockIdx.x * blockDim.x + threadIdx.x) >> 5;
    int lane = threadIdx.x & 31;
    if (w >= N_NODES) return;
    float di = rsqrtf(g_deg[w]);          // deg >= 1 always
    if (lane == 0) g_dinv[w] = di;
    float s = di * di;                    // self-loop: dinv*1*dinv
    float4 x = ((const float4*)X)[w * 32 + lane];
    ((float4*)g_agg)[w * 32 + lane] = make_float4(x.x * s, x.y * s, x.z * s, x.w * s);
}

// ---------------- scores + key histogram (warp per node) ----------------
__global__ void k_score(const float* __restrict__ X, const float* __restrict__ p) {
    __shared__ float4 ps[32];
    if (threadIdx.x < 32) ps[threadIdx.x] = ((const float4*)p)[threadIdx.x];
    __syncthreads();
    int w    = (blockIdx.x * blockDim.x + threadIdx.x) >> 5;
    int lane = threadIdx.x & 31;
    if (w >= N_NODES) return;
    float4 x  = ((const float4*)X)[w * 32 + lane];
    float4 pp = ps[lane];
    float d = x.x * pp.x + x.y * pp.y + x.z * pp.z + x.w * pp.w;
    for (int o = 16; o; o >>= 1) d += __shfl_xor_sync(0xffffffffu, d, o);
    if (lane == 0) {
        float s = d * g_pinv;
        unsigned bits = __float_as_uint(s);
        unsigned key  = (bits & 0x80000000u) ? ~bits : (bits ^ 0x80000000u);
        g_keys[w] = key;
        atomicAdd(&g_hist[key >> 16], 1);
    }
}

// ---------------- threshold bucket (1 block, 1024 threads) ----------------
__global__ void k_thresh() {
    __shared__ int csum[1024];
    int t = threadIdx.x;
    int s = 0;
    int base = t * 64;
    for (int b = 0; b < 64; b++) s += g_hist[base + b];
    csum[t] = s;
    __syncthreads();
    if (t == 0) {
        int cum = 0, chunk = 0;
        for (int c = 1023; c >= 0; c--) {
            if (cum + csum[c] >= C_DIM) { chunk = c; break; }
            cum += csum[c];
        }
        int B = chunk * 64;
        for (int b = chunk * 64 + 63; b >= chunk * 64; b--) {
            cum += g_hist[b];
            if (cum >= C_DIM) { B = b; break; }
        }
        g_thresh = B;
    }
}

// ---------------- compact candidates ----------------
__global__ void k_compact() {
    int i = blockIdx.x * 256 + threadIdx.x;
    if (i >= N_NODES) return;
    unsigned key = g_keys[i];
    if ((int)(key >> 16) >= g_thresh) {
        int pos = atomicAdd(&g_cnt, 1);
        if (pos < CANDMAX) { g_candk[pos] = key; g_candi[pos] = i; }
    }
}

// ---------------- exact top-128 sort + build X_tilde (1 block) ----------------
__global__ void k_topk(const float* __restrict__ X) {
    __shared__ unsigned long long s[CANDMAX];
    __shared__ int   sidx[C_DIM];
    __shared__ float sgate[C_DIM];
    int t = threadIdx.x;
    int cnt = g_cnt; if (cnt > CANDMAX) cnt = CANDMAX;
    for (int i = t; i < CANDMAX; i += 256) {
        if (i < cnt)
            s[i] = ((unsigned long long)g_candk[i] << 32) |
                   (unsigned)(0xFFFFFFFFu - (unsigned)g_candi[i]);  // tie: lower idx bigger
        else
            s[i] = 0ull;
    }
    __syncthreads();
    for (int k2 = 2; k2 <= CANDMAX; k2 <<= 1)
        for (int j = k2 >> 1; j > 0; j >>= 1) {
            for (int i = t; i < CANDMAX; i += 256) {
                int ixj = i ^ j;
                if (ixj > i) {
                    unsigned long long a = s[i], b = s[ixj];
                    bool asc = ((i & k2) == 0);
                    if (asc ? (a > b) : (a < b)) { s[i] = b; s[ixj] = a; }
                }
            }
            __syncthreads();
        }
    if (t < C_DIM) {
        unsigned long long comp = s[CANDMAX - 1 - t];      // rank t, descending
        unsigned key = (unsigned)(comp >> 32);
        int idx = (int)(0xFFFFFFFFu - (unsigned)comp);
        unsigned bits = (key & 0x80000000u) ? (key ^ 0x80000000u) : ~key;
        sidx[t]  = idx;
        sgate[t] = tanhf(__uint_as_float(bits));
    }
    __syncthreads();
    for (int i = t; i < C_DIM * C_DIM; i += 256) {
        int r = i >> 7, c = i & 127;
        g_Xt[i] = X[sidx[r] * C_DIM + c] * sgate[r];
    }
}

// ---------------- tiled SIMT GEMM: C[m,n] = sum_k A[m,k]*B[n,k] (+bias[n]) ----------------
// BM=64 rows/block, BN=128 cols per grid.y tile, K=128 whole.
// mode 0: A=g_Xt,  B=extB,   C=g_gi
// mode 1: A=extA,  B=extB,   C=g_gh
// mode 2: A=g_agg, B=g_Wnew, C=extC   (device-symbol B resolved ON DEVICE)
__global__ void __launch_bounds__(256)
k_gemm(int mode, const float* __restrict__ extA, const float* __restrict__ extB,
       float* __restrict__ extC, int M, int Nn, const float* __restrict__ bias) {
    const float* A; const float* B; float* Cm;
    if (mode == 0)      { A = g_Xt;  B = extB;   Cm = g_gi; }
    else if (mode == 1) { A = extA;  B = extB;   Cm = g_gh; }
    else                { A = g_agg; B = g_Wnew; Cm = extC; }

    extern __shared__ float sm[];
    float* Bs = sm;                 // [128][129] padded rows
    float* As = sm + 128 * 129;     // [64][128]
    int tid = threadIdx.x;
    int bx = blockIdx.x, by = blockIdx.y;

    #pragma unroll 4
    for (int it = 0; it < 64; it++) {                 // B tile 128x128
        int flat = tid + it * 256;
        int n = flat >> 7, k = flat & 127;
        Bs[n * 129 + k] = B[(by * 128 + n) * C_DIM + k];
    }
    int row0 = bx * 64;
    #pragma unroll 4
    for (int it = 0; it < 32; it++) {                 // A tile 64x128
        int flat = tid + it * 256;
        int r = flat >> 7, k = flat & 127;
        int gr = row0 + r;
        As[flat] = (gr < M) ? A[gr * C_DIM + k] : 0.0f;
    }
    __syncthreads();

    int tx = tid & 31, ty = tid >> 5;                 // cols: tx + 32*j (conflict-free)
    float acc[8][4];
    #pragma unroll
    for (int i = 0; i < 8; i++)
        #pragma unroll
        for (int j = 0; j < 4; j++) acc[i][j] = 0.0f;

    const float* Ap = As + ty * 8 * 128;
    const float* Bp = Bs + tx * 129;
    #pragma unroll 2
    for (int k4 = 0; k4 < 32; k4++) {
        float4 a4[8];
        #pragma unroll
        for (int i = 0; i < 8; i++)
            a4[i] = *(const float4*)(Ap + i * 128 + k4 * 4);
        #pragma unroll
        for (int j = 0; j < 4; j++) {
            const float* bp = Bp + j * (32 * 129) + k4 * 4;
            float b0 = bp[0], b1 = bp[1], b2 = bp[2], b3 = bp[3];
            #pragma unroll
            for (int i = 0; i < 8; i++)
                acc[i][j] += a4[i].x * b0 + a4[i].y * b1 + a4[i].z * b2 + a4[i].w * b3;
        }
    }
    #pragma unroll
    for (int i = 0; i < 8; i++) {
        int gr = row0 + ty * 8 + i;
        if (gr < M) {
            #pragma unroll
            for (int j = 0; j < 4; j++) {
                int col = tx + 32 * j;
                float v = acc[i][j];
                if (bias) v += bias[by * 128 + col];
                Cm[gr * Nn + by * 128 + col] = v;
            }
        }
    }
}

// ---------------- GRU gates -> W_new ----------------
__global__ void k_gates(const float* __restrict__ b_ih, const float* __restrict__ b_hh,
                        const float* __restrict__ Wc) {
    int i = blockIdx.x * 256 + threadIdx.x;
    if (i >= C_DIM * C_DIM) return;
    int b = i >> 7, j = i & 127;
    float gir = g_gi[b * 384 + j]       + b_ih[j];
    float ghr = g_gh[b * 384 + j]       + b_hh[j];
    float giz = g_gi[b * 384 + 128 + j] + b_ih[128 + j];
    float ghz = g_gh[b * 384 + 128 + j] + b_hh[128 + j];
    float gin = g_gi[b * 384 + 256 + j] + b_ih[256 + j];
    float ghn = g_gh[b * 384 + 256 + j] + b_hh[256 + j];
    float r = 1.0f / (1.0f + expf(-(gir + ghr)));
    float z = 1.0f / (1.0f + expf(-(giz + ghz)));
    float n = tanhf(gin + r * ghn);
    g_Wnew[i] = (1.0f - z) * n + z * Wc[i];
}

// ---------------- edge scatter: agg[dst] += X[src]*norm (warp/edge, red.v4) ----------------
__global__ void k_scatter(const float* __restrict__ X, const int* __restrict__ ei,
                          const float* __restrict__ ew) {
    int gw   = (blockIdx.x * blockDim.x + threadIdx.x) >> 5;
    int lane = threadIdx.x & 31;
    if (gw >= E_EDGES) return;
    int src = ei[gw];
    int dst = ei[E_EDGES + gw];
    float nrm = g_dinv[src] * ew[gw] * g_dinv[dst];
    float4 x = ((const float4*)X)[src * 32 + lane];
    float* ptr = g_agg + dst * C_DIM + lane * 4;
    asm volatile("red.global.add.v4.f32 [%0], {%1, %2, %3, %4};"
                 :: "l"(ptr), "f"(x.x * nrm), "f"(x.y * nrm), "f"(x.z * nrm), "f"(x.w * nrm)
                 : "memory");
}

// ---------------- launch ----------------
extern "C" void kernel_launch(void* const* d_in, const int* in_sizes, int n_in,
                              void* d_out, int out_size) {
    const float* X      = (const float*)d_in[0];
    const float* ew     = (const float*)d_in[1];
    const float* p      = (const float*)d_in[2];
    const float* W_ih   = (const float*)d_in[3];
    const float* W_hh   = (const float*)d_in[4];
    const float* b_ih   = (const float*)d_in[5];
    const float* b_hh   = (const float*)d_in[6];
    const float* W_conv = (const float*)d_in[7];
    const float* b_conv = (const float*)d_in[8];
    const int*   ei     = (const int*)d_in[9];     // int32 (JAX x64 disabled)
    float* out = (float*)d_out;

    const int GEMM_SMEM = (128 * 129 + 64 * 128) * sizeof(float);  // 98816 B
    cudaFuncSetAttribute(k_gemm, cudaFuncAttributeMaxDynamicSharedMemorySize, GEMM_SMEM);

    // normalization + aggregation chain (independent of topk/GRU)
    k_pnorm<<<1, 128>>>(p);
    k_init<<<256, 256>>>();
    k_deg<<<(E_EDGES + 255) / 256, 256>>>(ei, ew);
    k_dinv_agg<<<(N_NODES + 7) / 8, 256>>>(X);
    k_scatter<<<(E_EDGES + 7) / 8, 256>>>(X, ei, ew);

    // topk -> X_tilde
    k_score<<<(N_NODES + 7) / 8, 256>>>(X, p);
    k_thresh<<<1, 1024>>>();
    k_compact<<<(N_NODES + 255) / 256, 256>>>();
    k_topk<<<1, 256>>>(X);

    // GRU: gi = Xt @ W_ih^T, gh = W_conv @ W_hh^T, gates -> W_new
    k_gemm<<<dim3(2, 3), 256, GEMM_SMEM>>>(0, nullptr, W_ih, nullptr, C_DIM, 3 * C_DIM, nullptr);
    k_gemm<<<dim3(2, 3), 256, GEMM_SMEM>>>(1, W_conv, W_hh, nullptr, C_DIM, 3 * C_DIM, nullptr);
    k_gates<<<64, 256>>>(b_ih, b_hh, W_conv);

    // out = agg @ W_new^T + b_conv  (B = g_Wnew resolved on device)
    k_gemm<<<dim3((N_NODES + 63) / 64, 1), 256, GEMM_SMEM>>>(2, nullptr, nullptr, out,
                                                             N_NODES, C_DIM, b_conv);
}